// round 4
// baseline (speedup 1.0000x reference)
#include <cuda_runtime.h>
#include <cstdint>

#define NROWS  65536
#define HALFN  32768
#define DFEAT  48
#define HID    256
#define NSTEP  10
#define ROWS_PB 32
#define NBLOCKS (NROWS / ROWS_PB)

// ---------------- threefry2x32 (20 rounds) ---------------------------------
__host__ __device__ __forceinline__ unsigned rotl32(unsigned x, int d) {
#ifdef __CUDA_ARCH__
    return __funnelshift_l(x, x, d);
#else
    return (x << d) | (x >> (32 - d));
#endif
}

__host__ __device__ __forceinline__ void tf2x32(unsigned k0, unsigned k1,
                                                unsigned c0, unsigned c1,
                                                unsigned& o0, unsigned& o1) {
    unsigned ks2 = k0 ^ k1 ^ 0x1BD11BDAu;
    unsigned x0 = c0 + k0, x1 = c1 + k1;
#define TFR(r) { x0 += x1; x1 = rotl32(x1, (r)); x1 ^= x0; }
    TFR(13) TFR(15) TFR(26) TFR(6)
    x0 += k1;  x1 += ks2 + 1u;
    TFR(17) TFR(29) TFR(16) TFR(24)
    x0 += ks2; x1 += k0 + 2u;
    TFR(13) TFR(15) TFR(26) TFR(6)
    x0 += k0;  x1 += k1 + 3u;
    TFR(17) TFR(29) TFR(16) TFR(24)
    x0 += k1;  x1 += ks2 + 4u;
    TFR(13) TFR(15) TFR(26) TFR(6)
    x0 += ks2; x1 += k0 + 5u;
#undef TFR
    o0 = x0; o1 = x1;
}

// partitionable random_bits(32): xor of the two outputs at counter (0, i)
__device__ __forceinline__ unsigned rbits(unsigned k0, unsigned k1, unsigned i) {
    unsigned a, b;
    tf2x32(k0, k1, 0u, i, a, b);
    return a ^ b;
}

// ---------------- accurate exp/tanh (immune to --use_fast_math) -------------
__device__ __forceinline__ float my_expf(float x) {
    // n = round(x * log2e) via magic-number trick (valid |x| < ~3e5)
    float t = fmaf(x, 1.44269504088896341f, 12582912.0f);
    float n = __fadd_rn(t, -12582912.0f);
    // r = x - n*ln2 (split constants, Cephes)
    float r = fmaf(n, -0.693359375f, x);
    r = fmaf(n, 2.12194440e-4f, r);
    float p = 1.9875691500e-4f;
    p = fmaf(p, r, 1.3981999507e-3f);
    p = fmaf(p, r, 8.3334519073e-3f);
    p = fmaf(p, r, 4.1665795894e-2f);
    p = fmaf(p, r, 1.6666665459e-1f);
    p = fmaf(p, r, 5.0000001201e-1f);
    float er = fmaf(r * r, p, r) + 1.0f;           // e^r
    int ni = (int)n;
    float scale = __int_as_float((ni + 127) << 23); // 2^n (|n| small here)
    return er * scale;
}

__device__ __forceinline__ float my_tanh(float x) {
    float ax = fabsf(x);
    float e = my_expf(__fmul_rn(-2.0f, ax));
    float r = (1.0f - e) / (1.0f + e);
    if (ax > 9.0f) r = 1.0f;
    return copysignf(r, x);
}

// ---------------- XLA ErfInv32 ----------------------------------------------
__device__ __forceinline__ float jax_erfinv(float x) {
    float w = -log1pf(-__fmul_rn(x, x));
    float p;
    if (w < 5.0f) {
        w = __fadd_rn(w, -2.5f);
        p = 2.81022636e-08f;
        p = fmaf(p, w, 3.43273939e-07f);
        p = fmaf(p, w, -3.5233877e-06f);
        p = fmaf(p, w, -4.39150654e-06f);
        p = fmaf(p, w, 0.00021858087f);
        p = fmaf(p, w, -0.00125372503f);
        p = fmaf(p, w, -0.00417768164f);
        p = fmaf(p, w, 0.246640727f);
        p = fmaf(p, w, 1.50140941f);
    } else {
        w = __fadd_rn(sqrtf(w), -3.0f);
        p = -0.000200214257f;
        p = fmaf(p, w, 0.000100950558f);
        p = fmaf(p, w, 0.00134934322f);
        p = fmaf(p, w, -0.00367342844f);
        p = fmaf(p, w, 0.00573950773f);
        p = fmaf(p, w, -0.0076224613f);
        p = fmaf(p, w, 0.00943887047f);
        p = fmaf(p, w, 1.00167406f);
        p = fmaf(p, w, 2.83297682f);
    }
    return __fmul_rn(p, x);
}

__device__ __forceinline__ float bits_to_unit(unsigned bits) {
    return __fadd_rn(__uint_as_float((bits >> 9) | 0x3f800000u), -1.0f);
}

__device__ __forceinline__ float bits_to_normal(unsigned bits) {
    const float lo = __uint_as_float(0xbf7fffffu);   // nextafterf(-1,0)
    float f = bits_to_unit(bits);
    float u = __fadd_rn(__fmul_rn(f, 2.0f), lo);     // span rounds to exactly 2
    u = fmaxf(u, lo);
    return __fmul_rn(__uint_as_float(0x3fb504f3u), jax_erfinv(u));  // sqrt(2)
}

// ---------------- device scratch --------------------------------------------
__device__ float4   g_state[NROWS * 12];
__device__ unsigned g_keysA[NROWS], g_keysB[NROWS];
__device__ unsigned g_valsA[NROWS], g_valsB[NROWS];
__device__ unsigned g_hist[NROWS];      // 256 digits x 256 blocks

struct StepKeys { unsigned k[NSTEP][4][2]; };

// ---------------- fused MH chain kernel -------------------------------------
#define SMEM_FLOATS (DFEAT*HID + HID + HID + ROWS_PB*DFEAT + ROWS_PB*DFEAT)
#define SMEM_BYTES  (SMEM_FLOATS * 4)

__device__ __forceinline__ void eval_rows(const float* __restrict__ buf,
                                          const float* __restrict__ sW,
                                          const float* __restrict__ sb,
                                          const float* __restrict__ sw2,
                                          int r0, int lane, float la[4]) {
    float acc[4][8];
#pragma unroll
    for (int r = 0; r < 4; r++)
#pragma unroll
        for (int j = 0; j < 8; j++) acc[r][j] = 0.0f;

#pragma unroll 4
    for (int k = 0; k < DFEAT; k += 4) {
#pragma unroll
        for (int kk = 0; kk < 4; kk++) {
            float4 w0 = *(const float4*)&sW[(k + kk) * HID + lane * 4];
            float4 w1 = *(const float4*)&sW[(k + kk) * HID + 128 + lane * 4];
#pragma unroll
            for (int r = 0; r < 4; r++) {
                float fk = buf[(r0 + r) * DFEAT + k + kk];
                acc[r][0] = fmaf(fk, w0.x, acc[r][0]);
                acc[r][1] = fmaf(fk, w0.y, acc[r][1]);
                acc[r][2] = fmaf(fk, w0.z, acc[r][2]);
                acc[r][3] = fmaf(fk, w0.w, acc[r][3]);
                acc[r][4] = fmaf(fk, w1.x, acc[r][4]);
                acc[r][5] = fmaf(fk, w1.y, acc[r][5]);
                acc[r][6] = fmaf(fk, w1.z, acc[r][6]);
                acc[r][7] = fmaf(fk, w1.w, acc[r][7]);
            }
        }
    }
    float4 b0 = *(const float4*)&sb[lane * 4];
    float4 b1 = *(const float4*)&sb[128 + lane * 4];
    float4 v0 = *(const float4*)&sw2[lane * 4];
    float4 v1 = *(const float4*)&sw2[128 + lane * 4];
#pragma unroll
    for (int r = 0; r < 4; r++) {
        float s = my_tanh(acc[r][0] + b0.x) * v0.x;
        s = fmaf(my_tanh(acc[r][1] + b0.y), v0.y, s);
        s = fmaf(my_tanh(acc[r][2] + b0.z), v0.z, s);
        s = fmaf(my_tanh(acc[r][3] + b0.w), v0.w, s);
        s = fmaf(my_tanh(acc[r][4] + b1.x), v1.x, s);
        s = fmaf(my_tanh(acc[r][5] + b1.y), v1.y, s);
        s = fmaf(my_tanh(acc[r][6] + b1.z), v1.z, s);
        s = fmaf(my_tanh(acc[r][7] + b1.w), v1.w, s);
#pragma unroll
        for (int off = 16; off; off >>= 1)
            s += __shfl_xor_sync(0xffffffffu, s, off);
        la[r] = s;
    }
}

__global__ void __launch_bounds__(256, 2)
chain_kernel(const float* __restrict__ x,
             const float* __restrict__ W1, const float* __restrict__ b1,
             const float* __restrict__ w2, const float* __restrict__ Wh,
             const float* __restrict__ bh, const float* __restrict__ wh2,
             StepKeys sk) {
    extern __shared__ float smem[];
    float* sW  = smem;
    float* sb  = sW + DFEAT * HID;
    float* sw2 = sb + HID;
    float* sS  = sw2 + HID;
    float* sP  = sS + ROWS_PB * DFEAT;

    int tid = threadIdx.x;
    int half = (int)(blockIdx.x >> 10);
    int localBase = (int)(blockIdx.x & 1023) * ROWS_PB;
    int rowBase = half * HALFN + localBase;

    const float* W  = half ? Wh  : W1;
    const float* bb = half ? bh  : b1;
    const float* vv = half ? wh2 : w2;

    for (int i = tid; i < DFEAT * HID; i += 256) sW[i] = W[i];
    sb[tid]  = bb[tid];
    sw2[tid] = vv[tid];
    {
        const float4* xin = (const float4*)x;
        float4* s4 = (float4*)sS;
        for (int e = tid; e < ROWS_PB * 12; e += 256)
            s4[e] = xin[rowBase * 12 + e];
    }
    __syncthreads();

    int warp = tid >> 5, lane = tid & 31;
    int r0 = warp * 4;

    float la[4], pcur[4];
    eval_rows(sS, sW, sb, sw2, r0, lane, la);
#pragma unroll
    for (int r = 0; r < 4; r++) pcur[r] = my_expf(__fmul_rn(2.0f, la[r]));

    for (int t = 0; t < NSTEP; t++) {
        __syncthreads();
        unsigned n0 = sk.k[t][half ? 1 : 0][0], n1 = sk.k[t][half ? 1 : 0][1];
        unsigned u0 = sk.k[t][half ? 3 : 2][0], u1 = sk.k[t][half ? 3 : 2][1];

        for (int e = tid; e < ROWS_PB * DFEAT; e += 256) {
            unsigned flat = (unsigned)(localBase * DFEAT + e);
            float nrm = bits_to_normal(rbits(n0, n1, flat));
            sP[e] = __fadd_rn(sS[e], __fmul_rn(0.02f, nrm));
        }
        __syncthreads();

        eval_rows(sP, sW, sb, sw2, r0, lane, la);
#pragma unroll
        for (int r = 0; r < 4; r++) {
            float pnew = my_expf(__fmul_rn(2.0f, la[r]));
            float uu = bits_to_unit(rbits(u0, u1, (unsigned)(localBase + r0 + r)));
            if (pnew / pcur[r] > uu) {          // warp-uniform branch
                pcur[r] = pnew;
                int base = (r0 + r) * DFEAT;
                sS[base + lane] = sP[base + lane];
                if (lane < 16) sS[base + 32 + lane] = sP[base + 32 + lane];
            }
        }
    }
    __syncthreads();
    {
        float4* s4 = (float4*)sS;
        for (int e = tid; e < ROWS_PB * 12; e += 256)
            g_state[rowBase * 12 + e] = s4[e];
    }
}

// ---------------- permutation: 2 rounds of stable LSD radix sort ------------
__global__ void genkeys_kernel(unsigned k0, unsigned k1, int initVals) {
    int i = blockIdx.x * blockDim.x + threadIdx.x;
    g_keysA[i] = rbits(k0, k1, (unsigned)i);
    if (initVals) g_valsA[i] = (unsigned)i;
}

__global__ void radix_count(int srcB, int shift) {
    __shared__ unsigned h[256];
    const unsigned* keys = srcB ? g_keysB : g_keysA;
    h[threadIdx.x] = 0;
    __syncthreads();
    unsigned d = (keys[blockIdx.x * 256 + threadIdx.x] >> shift) & 255u;
    atomicAdd(&h[d], 1u);
    __syncthreads();
    g_hist[threadIdx.x * 256 + blockIdx.x] = h[threadIdx.x];
}

__global__ void radix_scan() {              // 1 block x 1024
    __shared__ unsigned sh_warp[32];
    __shared__ unsigned sh_carry;
    int tid = threadIdx.x, lane = tid & 31, wid = tid >> 5;
    if (tid == 0) sh_carry = 0;
    __syncthreads();
    for (int chunk = 0; chunk < NROWS; chunk += 1024) {
        unsigned v = g_hist[chunk + tid];
        unsigned inc = v;
#pragma unroll
        for (int off = 1; off < 32; off <<= 1) {
            unsigned tmp = __shfl_up_sync(0xffffffffu, inc, off);
            if (lane >= off) inc += tmp;
        }
        if (lane == 31) sh_warp[wid] = inc;
        __syncthreads();
        if (wid == 0) {
            unsigned w = sh_warp[lane];
            unsigned wi = w;
#pragma unroll
            for (int off = 1; off < 32; off <<= 1) {
                unsigned tmp = __shfl_up_sync(0xffffffffu, wi, off);
                if (lane >= off) wi += tmp;
            }
            sh_warp[lane] = wi - w;
        }
        __syncthreads();
        unsigned exc = inc - v + sh_warp[wid] + sh_carry;
        g_hist[chunk + tid] = exc;
        __syncthreads();
        if (tid == 1023) sh_carry = exc + v;
        __syncthreads();
    }
}

__global__ void radix_scatter(int srcB, int shift) {
    __shared__ unsigned sd[256];
    const unsigned* kin = srcB ? g_keysB : g_keysA;
    const unsigned* vin = srcB ? g_valsB : g_valsA;
    unsigned* kout = srcB ? g_keysA : g_keysB;
    unsigned* vout = srcB ? g_valsA : g_valsB;
    int i = blockIdx.x * 256 + threadIdx.x;
    unsigned k = kin[i];
    unsigned d = (k >> shift) & 255u;
    sd[threadIdx.x] = d;
    __syncthreads();
    unsigned rank = 0;
    for (int j = 0; j < (int)threadIdx.x; j++) rank += (sd[j] == d);
    unsigned pos = g_hist[d * 256 + blockIdx.x] + rank;
    kout[pos] = k;
    vout[pos] = vin[i];
}

__global__ void gather_kernel(float4* __restrict__ out) {
    int idx = blockIdx.x * blockDim.x + threadIdx.x;
    int row = idx / 12, q = idx - row * 12;
    out[idx] = g_state[g_valsA[row] * 12 + q];
}

// ---------------- host ------------------------------------------------------
extern "C" void kernel_launch(void* const* d_in, const int* in_sizes, int n_in,
                              void* d_out, int out_size) {
    (void)in_sizes; (void)n_in; (void)out_size;
    const float* x   = (const float*)d_in[0];
    const float* W1  = (const float*)d_in[1];
    const float* b1  = (const float*)d_in[2];
    const float* w2  = (const float*)d_in[3];
    const float* Wh  = (const float*)d_in[4];
    const float* bh  = (const float*)d_in[5];
    const float* wh2 = (const float*)d_in[6];

    // step keys: split(key(42), 10) then split(step_key, 4)
    StepKeys sk;
    for (int t = 0; t < NSTEP; t++) {
        unsigned s0, s1;
        tf2x32(0u, 42u, 0u, (unsigned)t, s0, s1);
        for (int j = 0; j < 4; j++)
            tf2x32(s0, s1, 0u, (unsigned)j, sk.k[t][j][0], sk.k[t][j][1]);
    }
    // permutation subkeys: key(7); (key, sub1) = split(key); (.., sub2) = split(key')
    unsigned nk0, nk1, s1a, s1b, s2a, s2b;
    tf2x32(0u, 7u, 0u, 0u, nk0, nk1);
    tf2x32(0u, 7u, 0u, 1u, s1a, s1b);
    tf2x32(nk0, nk1, 0u, 1u, s2a, s2b);

    cudaFuncSetAttribute(chain_kernel,
                         cudaFuncAttributeMaxDynamicSharedMemorySize, SMEM_BYTES);
    chain_kernel<<<NBLOCKS, 256, SMEM_BYTES>>>(x, W1, b1, w2, Wh, bh, wh2, sk);

    for (int round = 0; round < 2; round++) {
        if (round == 0) genkeys_kernel<<<NROWS / 256, 256>>>(s1a, s1b, 1);
        else            genkeys_kernel<<<NROWS / 256, 256>>>(s2a, s2b, 0);
        for (int pass = 0; pass < 4; pass++) {
            radix_count<<<256, 256>>>(pass & 1, pass * 8);
            radix_scan<<<1, 1024>>>();
            radix_scatter<<<256, 256>>>(pass & 1, pass * 8);
        }
    }
    gather_kernel<<<NROWS * 12 / 256, 256>>>((float4*)d_out);
}

// round 8
// speedup vs baseline: 1.4505x; 1.4505x over previous
#include <cuda_runtime.h>
#include <cstdint>

#define NROWS  65536
#define HALFN  32768
#define DFEAT  48
#define HID    256
#define NSTEP  10
#define ROWS_PB 32
#define NBLOCKS (NROWS / ROWS_PB)

typedef unsigned long long u64;

// ---------------- packed f32x2 helpers (sm_103a FFMA2) ----------------------
__device__ __forceinline__ u64 pack2(float lo, float hi) {
    u64 r; asm("mov.b64 %0, {%1, %2};" : "=l"(r) : "f"(lo), "f"(hi)); return r;
}
__device__ __forceinline__ void unpack2(u64 v, float& lo, float& hi) {
    asm("mov.b64 {%0, %1}, %2;" : "=f"(lo), "=f"(hi) : "l"(v));
}
__device__ __forceinline__ u64 ffma2(u64 a, u64 b, u64 c) {
    u64 d; asm("fma.rn.f32x2 %0, %1, %2, %3;" : "=l"(d) : "l"(a), "l"(b), "l"(c));
    return d;
}

// ---------------- threefry2x32 (20 rounds) ---------------------------------
__host__ __device__ __forceinline__ unsigned rotl32(unsigned x, int d) {
#ifdef __CUDA_ARCH__
    return __funnelshift_l(x, x, d);
#else
    return (x << d) | (x >> (32 - d));
#endif
}

__host__ __device__ __forceinline__ void tf2x32(unsigned k0, unsigned k1,
                                                unsigned c0, unsigned c1,
                                                unsigned& o0, unsigned& o1) {
    unsigned ks2 = k0 ^ k1 ^ 0x1BD11BDAu;
    unsigned x0 = c0 + k0, x1 = c1 + k1;
#define TFR(r) { x0 += x1; x1 = rotl32(x1, (r)); x1 ^= x0; }
    TFR(13) TFR(15) TFR(26) TFR(6)
    x0 += k1;  x1 += ks2 + 1u;
    TFR(17) TFR(29) TFR(16) TFR(24)
    x0 += ks2; x1 += k0 + 2u;
    TFR(13) TFR(15) TFR(26) TFR(6)
    x0 += k0;  x1 += k1 + 3u;
    TFR(17) TFR(29) TFR(16) TFR(24)
    x0 += k1;  x1 += ks2 + 4u;
    TFR(13) TFR(15) TFR(26) TFR(6)
    x0 += ks2; x1 += k0 + 5u;
#undef TFR
    o0 = x0; o1 = x1;
}

__device__ __forceinline__ unsigned rbits(unsigned k0, unsigned k1, unsigned i) {
    unsigned a, b;
    tf2x32(k0, k1, 0u, i, a, b);
    return a ^ b;
}

// ---------------- accurate exp/tanh (fast-math-proof, MUFU-free) ------------
__device__ __forceinline__ float my_expf(float x) {
    float t = fmaf(x, 1.44269504088896341f, 12582912.0f);
    float n = __fadd_rn(t, -12582912.0f);
    float r = fmaf(n, -0.693359375f, x);
    r = fmaf(n, 2.12194440e-4f, r);
    float p = 1.9875691500e-4f;
    p = fmaf(p, r, 1.3981999507e-3f);
    p = fmaf(p, r, 8.3334519073e-3f);
    p = fmaf(p, r, 4.1665795894e-2f);
    p = fmaf(p, r, 1.6666665459e-1f);
    p = fmaf(p, r, 5.0000001201e-1f);
    float er = fmaf(r * r, p, r) + 1.0f;
    int ni = (int)n;
    float scale = __int_as_float((ni + 127) << 23);
    return er * scale;
}

// reciprocal for d in [1,2]: bit-trick seed + 3 Newton steps (FMA pipe only)
__device__ __forceinline__ float fast_rcp(float d) {
    float r = __int_as_float(0x7EF311C3 - __float_as_int(d));
    r = __fmul_rn(r, fmaf(-d, r, 2.0f));
    r = __fmul_rn(r, fmaf(-d, r, 2.0f));
    r = fmaf(fmaf(-d, r, 1.0f), r, r);
    return r;
}

__device__ __forceinline__ float my_tanh(float x) {
    float ax = fabsf(x);
    float e = my_expf(__fmul_rn(-2.0f, ax));
    float r = __fmul_rn(__fadd_rn(1.0f, -e), fast_rcp(__fadd_rn(1.0f, e)));
    if (ax > 9.0f) r = 1.0f;
    return copysignf(r, x);
}

// ---------------- XLA ErfInv32 ----------------------------------------------
__device__ __forceinline__ float jax_erfinv(float x) {
    float w = -log1pf(-__fmul_rn(x, x));
    float p;
    if (w < 5.0f) {
        w = __fadd_rn(w, -2.5f);
        p = 2.81022636e-08f;
        p = fmaf(p, w, 3.43273939e-07f);
        p = fmaf(p, w, -3.5233877e-06f);
        p = fmaf(p, w, -4.39150654e-06f);
        p = fmaf(p, w, 0.00021858087f);
        p = fmaf(p, w, -0.00125372503f);
        p = fmaf(p, w, -0.00417768164f);
        p = fmaf(p, w, 0.246640727f);
        p = fmaf(p, w, 1.50140941f);
    } else {
        w = __fadd_rn(sqrtf(w), -3.0f);
        p = -0.000200214257f;
        p = fmaf(p, w, 0.000100950558f);
        p = fmaf(p, w, 0.00134934322f);
        p = fmaf(p, w, -0.00367342844f);
        p = fmaf(p, w, 0.00573950773f);
        p = fmaf(p, w, -0.0076224613f);
        p = fmaf(p, w, 0.00943887047f);
        p = fmaf(p, w, 1.00167406f);
        p = fmaf(p, w, 2.83297682f);
    }
    return __fmul_rn(p, x);
}

__device__ __forceinline__ float bits_to_unit(unsigned bits) {
    return __fadd_rn(__uint_as_float((bits >> 9) | 0x3f800000u), -1.0f);
}

__device__ __forceinline__ float bits_to_normal(unsigned bits) {
    const float lo = __uint_as_float(0xbf7fffffu);
    float f = bits_to_unit(bits);
    float u = __fadd_rn(__fmul_rn(f, 2.0f), lo);
    u = fmaxf(u, lo);
    return __fmul_rn(__uint_as_float(0x3fb504f3u), jax_erfinv(u));
}

// ---------------- device scratch --------------------------------------------
__device__ float4   g_state[NROWS * 12];
__device__ unsigned g_keysA[NROWS], g_keysB[NROWS];
__device__ unsigned g_valsA[NROWS], g_valsB[NROWS];
__device__ unsigned g_hist[NROWS];      // 256 digits x 256 blocks
__device__ unsigned g_rowsum[256];
__device__ unsigned g_rowoff[256];

struct StepKeys { unsigned k[NSTEP][4][2]; };

// ---------------- fused MH chain kernel -------------------------------------
#define SMEM_FLOATS (DFEAT*HID + HID + HID + ROWS_PB*DFEAT + ROWS_PB*DFEAT)
#define SMEM_BYTES  (SMEM_FLOATS * 4)

__device__ __forceinline__ void eval_rows(const float* __restrict__ buf,
                                          const float* __restrict__ sW,
                                          const float* __restrict__ sb,
                                          const float* __restrict__ sw2,
                                          int r0, int lane, float la[4]) {
    u64 acc[4][4];
#pragma unroll
    for (int r = 0; r < 4; r++)
#pragma unroll
        for (int j = 0; j < 4; j++) acc[r][j] = 0ull;

#pragma unroll 4
    for (int k = 0; k < DFEAT; k += 4) {
#pragma unroll
        for (int kk = 0; kk < 4; kk++) {
            ulonglong2 w0 = *(const ulonglong2*)&sW[(k + kk) * HID + lane * 4];
            ulonglong2 w1 = *(const ulonglong2*)&sW[(k + kk) * HID + 128 + lane * 4];
#pragma unroll
            for (int r = 0; r < 4; r++) {
                float fk = buf[(r0 + r) * DFEAT + k + kk];
                u64 f2 = pack2(fk, fk);
                acc[r][0] = ffma2(f2, w0.x, acc[r][0]);
                acc[r][1] = ffma2(f2, w0.y, acc[r][1]);
                acc[r][2] = ffma2(f2, w1.x, acc[r][2]);
                acc[r][3] = ffma2(f2, w1.y, acc[r][3]);
            }
        }
    }
    float4 b0 = *(const float4*)&sb[lane * 4];
    float4 b1 = *(const float4*)&sb[128 + lane * 4];
    float4 v0 = *(const float4*)&sw2[lane * 4];
    float4 v1 = *(const float4*)&sw2[128 + lane * 4];
#pragma unroll
    for (int r = 0; r < 4; r++) {
        float a0, a1, a2, a3, a4, a5, a6, a7;
        unpack2(acc[r][0], a0, a1);
        unpack2(acc[r][1], a2, a3);
        unpack2(acc[r][2], a4, a5);
        unpack2(acc[r][3], a6, a7);
        float s = my_tanh(a0 + b0.x) * v0.x;
        s = fmaf(my_tanh(a1 + b0.y), v0.y, s);
        s = fmaf(my_tanh(a2 + b0.z), v0.z, s);
        s = fmaf(my_tanh(a3 + b0.w), v0.w, s);
        s = fmaf(my_tanh(a4 + b1.x), v1.x, s);
        s = fmaf(my_tanh(a5 + b1.y), v1.y, s);
        s = fmaf(my_tanh(a6 + b1.z), v1.z, s);
        s = fmaf(my_tanh(a7 + b1.w), v1.w, s);
#pragma unroll
        for (int off = 16; off; off >>= 1)
            s += __shfl_xor_sync(0xffffffffu, s, off);
        la[r] = s;
    }
}

__global__ void __launch_bounds__(256, 2)
chain_kernel(const float* __restrict__ x,
             const float* __restrict__ W1, const float* __restrict__ b1,
             const float* __restrict__ w2, const float* __restrict__ Wh,
             const float* __restrict__ bh, const float* __restrict__ wh2,
             StepKeys sk) {
    extern __shared__ float smem[];
    float* sW  = smem;
    float* sb  = sW + DFEAT * HID;
    float* sw2 = sb + HID;
    float* sS  = sw2 + HID;
    float* sP  = sS + ROWS_PB * DFEAT;

    int tid = threadIdx.x;
    int half = (int)(blockIdx.x >> 10);
    int localBase = (int)(blockIdx.x & 1023) * ROWS_PB;
    int rowBase = half * HALFN + localBase;

    const float* W  = half ? Wh  : W1;
    const float* bb = half ? bh  : b1;
    const float* vv = half ? wh2 : w2;

    for (int i = tid; i < DFEAT * HID; i += 256) sW[i] = W[i];
    sb[tid]  = bb[tid];
    sw2[tid] = vv[tid];
    {
        const float4* xin = (const float4*)x;
        float4* s4 = (float4*)sS;
        for (int e = tid; e < ROWS_PB * 12; e += 256)
            s4[e] = xin[rowBase * 12 + e];
    }
    __syncthreads();

    int warp = tid >> 5, lane = tid & 31;
    int r0 = warp * 4;

    float la[4], pcur[4];
    eval_rows(sS, sW, sb, sw2, r0, lane, la);
#pragma unroll
    for (int r = 0; r < 4; r++) pcur[r] = my_expf(__fmul_rn(2.0f, la[r]));

    for (int t = 0; t < NSTEP; t++) {
        __syncthreads();
        unsigned n0 = sk.k[t][half ? 1 : 0][0], n1 = sk.k[t][half ? 1 : 0][1];
        unsigned u0 = sk.k[t][half ? 3 : 2][0], u1 = sk.k[t][half ? 3 : 2][1];

        for (int e = tid; e < ROWS_PB * DFEAT; e += 256) {
            unsigned flat = (unsigned)(localBase * DFEAT + e);
            float nrm = bits_to_normal(rbits(n0, n1, flat));
            sP[e] = __fadd_rn(sS[e], __fmul_rn(0.02f, nrm));
        }
        __syncthreads();

        eval_rows(sP, sW, sb, sw2, r0, lane, la);
#pragma unroll
        for (int r = 0; r < 4; r++) {
            float pnew = my_expf(__fmul_rn(2.0f, la[r]));
            float uu = bits_to_unit(rbits(u0, u1, (unsigned)(localBase + r0 + r)));
            if (pnew / pcur[r] > uu) {          // warp-uniform branch
                pcur[r] = pnew;
                int base = (r0 + r) * DFEAT;
                sS[base + lane] = sP[base + lane];
                if (lane < 16) sS[base + 32 + lane] = sP[base + 32 + lane];
            }
        }
    }
    __syncthreads();
    {
        float4* s4 = (float4*)sS;
        for (int e = tid; e < ROWS_PB * 12; e += 256)
            g_state[rowBase * 12 + e] = s4[e];
    }
}

// ---------------- permutation: 2 rounds of stable LSD radix sort ------------
__global__ void genkeys_kernel(unsigned k0, unsigned k1, int initVals) {
    int i = blockIdx.x * blockDim.x + threadIdx.x;
    g_keysA[i] = rbits(k0, k1, (unsigned)i);
    if (initVals) g_valsA[i] = (unsigned)i;
}

__global__ void radix_count(int srcB, int shift) {
    __shared__ unsigned h[256];
    const unsigned* keys = srcB ? g_keysB : g_keysA;
    h[threadIdx.x] = 0;
    __syncthreads();
    unsigned d = (keys[blockIdx.x * 256 + threadIdx.x] >> shift) & 255u;
    atomicAdd(&h[d], 1u);
    __syncthreads();
    g_hist[threadIdx.x * 256 + blockIdx.x] = h[threadIdx.x];
}

// per-digit-row exclusive scan: 256 blocks x 256 threads
__global__ void radix_scan_rows() {
    __shared__ unsigned wsum[8];
    int d = blockIdx.x, t = threadIdx.x, lane = t & 31, w = t >> 5;
    unsigned v = g_hist[d * 256 + t];
    unsigned inc = v;
#pragma unroll
    for (int off = 1; off < 32; off <<= 1) {
        unsigned tmp = __shfl_up_sync(0xffffffffu, inc, off);
        if (lane >= off) inc += tmp;
    }
    if (lane == 31) wsum[w] = inc;
    __syncthreads();
    unsigned woff = 0;
#pragma unroll
    for (int i = 0; i < 8; i++) woff += (i < w) ? wsum[i] : 0u;
    unsigned exc = inc - v + woff;
    g_hist[d * 256 + t] = exc;
    if (t == 255) g_rowsum[d] = exc + v;
}

// scan of the 256 row totals: 1 block x 256 threads
__global__ void radix_scan_tot() {
    __shared__ unsigned wsum[8];
    int t = threadIdx.x, lane = t & 31, w = t >> 5;
    unsigned v = g_rowsum[t];
    unsigned inc = v;
#pragma unroll
    for (int off = 1; off < 32; off <<= 1) {
        unsigned tmp = __shfl_up_sync(0xffffffffu, inc, off);
        if (lane >= off) inc += tmp;
    }
    if (lane == 31) wsum[w] = inc;
    __syncthreads();
    unsigned woff = 0;
#pragma unroll
    for (int i = 0; i < 8; i++) woff += (i < w) ? wsum[i] : 0u;
    g_rowoff[t] = inc - v + woff;
}

// stable scatter with warp-ballot ranking (replaces O(tid) serial rank loop)
__global__ void radix_scatter(int srcB, int shift) {
    __shared__ unsigned wh[8][256];     // per-warp per-digit counts
    const unsigned* kin = srcB ? g_keysB : g_keysA;
    const unsigned* vin = srcB ? g_valsB : g_valsA;
    unsigned* kout = srcB ? g_keysA : g_keysB;
    unsigned* vout = srcB ? g_valsA : g_valsB;
    int t = threadIdx.x, w = t >> 5, lane = t & 31;
#pragma unroll
    for (int i = 0; i < 8; i++) wh[i][t] = 0;
    __syncthreads();

    int i = blockIdx.x * 256 + t;
    unsigned k = kin[i];
    unsigned v = vin[i];
    unsigned d = (k >> shift) & 255u;
    unsigned mask = __match_any_sync(0xffffffffu, d);
    unsigned rankw = __popc(mask & ((1u << lane) - 1u));
    if (rankw == 0) wh[w][d] = __popc(mask);   // leader publishes warp count
    __syncthreads();
    unsigned prev = 0;
#pragma unroll
    for (int j = 0; j < 8; j++) prev += (j < w) ? wh[j][d] : 0u;
    unsigned pos = g_hist[d * 256 + blockIdx.x] + g_rowoff[d] + prev + rankw;
    kout[pos] = k;
    vout[pos] = v;
}

__global__ void gather_kernel(float4* __restrict__ out) {
    int idx = blockIdx.x * blockDim.x + threadIdx.x;
    int row = idx / 12, q = idx - row * 12;
    out[idx] = g_state[g_valsA[row] * 12 + q];
}

// ---------------- host ------------------------------------------------------
extern "C" void kernel_launch(void* const* d_in, const int* in_sizes, int n_in,
                              void* d_out, int out_size) {
    (void)in_sizes; (void)n_in; (void)out_size;
    const float* x   = (const float*)d_in[0];
    const float* W1  = (const float*)d_in[1];
    const float* b1  = (const float*)d_in[2];
    const float* w2  = (const float*)d_in[3];
    const float* Wh  = (const float*)d_in[4];
    const float* bh  = (const float*)d_in[5];
    const float* wh2 = (const float*)d_in[6];

    StepKeys sk;
    for (int t = 0; t < NSTEP; t++) {
        unsigned s0, s1;
        tf2x32(0u, 42u, 0u, (unsigned)t, s0, s1);
        for (int j = 0; j < 4; j++)
            tf2x32(s0, s1, 0u, (unsigned)j, sk.k[t][j][0], sk.k[t][j][1]);
    }
    unsigned nk0, nk1, s1a, s1b, s2a, s2b;
    tf2x32(0u, 7u, 0u, 0u, nk0, nk1);
    tf2x32(0u, 7u, 0u, 1u, s1a, s1b);
    tf2x32(nk0, nk1, 0u, 1u, s2a, s2b);

    cudaFuncSetAttribute(chain_kernel,
                         cudaFuncAttributeMaxDynamicSharedMemorySize, SMEM_BYTES);
    chain_kernel<<<NBLOCKS, 256, SMEM_BYTES>>>(x, W1, b1, w2, Wh, bh, wh2, sk);

    for (int round = 0; round < 2; round++) {
        if (round == 0) genkeys_kernel<<<NROWS / 256, 256>>>(s1a, s1b, 1);
        else            genkeys_kernel<<<NROWS / 256, 256>>>(s2a, s2b, 0);
        for (int pass = 0; pass < 4; pass++) {
            radix_count<<<256, 256>>>(pass & 1, pass * 8);
            radix_scan_rows<<<256, 256>>>();
            radix_scan_tot<<<1, 256>>>();
            radix_scatter<<<256, 256>>>(pass & 1, pass * 8);
        }
    }
    gather_kernel<<<NROWS * 12 / 256, 256>>>((float4*)d_out);
}

// round 9
// speedup vs baseline: 1.4612x; 1.0074x over previous
#include <cuda_runtime.h>
#include <cstdint>

#define NROWS  65536
#define HALFN  32768
#define DFEAT  48
#define HID    256
#define NSTEP  10
#define ROWS_PB 32
#define NBLOCKS (NROWS / ROWS_PB)

typedef unsigned long long u64;

// ---------------- packed f32x2 helpers (sm_103a FFMA2/FMUL2/FADD2) ----------
__device__ __forceinline__ u64 pack2(float lo, float hi) {
    u64 r; asm("mov.b64 %0, {%1, %2};" : "=l"(r) : "f"(lo), "f"(hi)); return r;
}
__device__ __forceinline__ void unpack2(u64 v, float& lo, float& hi) {
    asm("mov.b64 {%0, %1}, %2;" : "=f"(lo), "=f"(hi) : "l"(v));
}
__device__ __forceinline__ u64 ffma2(u64 a, u64 b, u64 c) {
    u64 d; asm("fma.rn.f32x2 %0, %1, %2, %3;" : "=l"(d) : "l"(a), "l"(b), "l"(c));
    return d;
}
__device__ __forceinline__ u64 mul2(u64 a, u64 b) {
    u64 d; asm("mul.rn.f32x2 %0, %1, %2;" : "=l"(d) : "l"(a), "l"(b)); return d;
}
__device__ __forceinline__ u64 add2(u64 a, u64 b) {
    u64 d; asm("add.rn.f32x2 %0, %1, %2;" : "=l"(d) : "l"(a), "l"(b)); return d;
}
__device__ __forceinline__ u64 bcast2(float f) {
    unsigned b = __float_as_uint(f); return (((u64)b) << 32) | (u64)b;
}

// ---------------- threefry2x32 (20 rounds) ---------------------------------
__host__ __device__ __forceinline__ unsigned rotl32(unsigned x, int d) {
#ifdef __CUDA_ARCH__
    return __funnelshift_l(x, x, d);
#else
    return (x << d) | (x >> (32 - d));
#endif
}

__host__ __device__ __forceinline__ void tf2x32(unsigned k0, unsigned k1,
                                                unsigned c0, unsigned c1,
                                                unsigned& o0, unsigned& o1) {
    unsigned ks2 = k0 ^ k1 ^ 0x1BD11BDAu;
    unsigned x0 = c0 + k0, x1 = c1 + k1;
#define TFR(r) { x0 += x1; x1 = rotl32(x1, (r)); x1 ^= x0; }
    TFR(13) TFR(15) TFR(26) TFR(6)
    x0 += k1;  x1 += ks2 + 1u;
    TFR(17) TFR(29) TFR(16) TFR(24)
    x0 += ks2; x1 += k0 + 2u;
    TFR(13) TFR(15) TFR(26) TFR(6)
    x0 += k0;  x1 += k1 + 3u;
    TFR(17) TFR(29) TFR(16) TFR(24)
    x0 += k1;  x1 += ks2 + 4u;
    TFR(13) TFR(15) TFR(26) TFR(6)
    x0 += ks2; x1 += k0 + 5u;
#undef TFR
    o0 = x0; o1 = x1;
}

__device__ __forceinline__ unsigned rbits(unsigned k0, unsigned k1, unsigned i) {
    unsigned a, b;
    tf2x32(k0, k1, 0u, i, a, b);
    return a ^ b;
}

// ---------------- accurate exp (fast-math-proof, MUFU-free), scalar ---------
__device__ __forceinline__ float my_expf(float x) {
    float t = fmaf(x, 1.44269504088896341f, 12582912.0f);
    float n = __fadd_rn(t, -12582912.0f);
    float r = fmaf(n, -0.693359375f, x);
    r = fmaf(n, 2.12194440e-4f, r);
    float p = 1.9875691500e-4f;
    p = fmaf(p, r, 1.3981999507e-3f);
    p = fmaf(p, r, 8.3334519073e-3f);
    p = fmaf(p, r, 4.1665795894e-2f);
    p = fmaf(p, r, 1.6666665459e-1f);
    p = fmaf(p, r, 5.0000001201e-1f);
    float er = fmaf(r * r, p, r) + 1.0f;
    int ni = (int)n;
    float scale = __int_as_float((ni + 127) << 23);
    return er * scale;
}

// ---------------- packed tanh pair: bit-identical per half to the scalar
// my_tanh (exp Cephes + bit-seed Newton rcp), but running on f32x2 pipes.
__device__ __forceinline__ void tanh2(float x0, float x1, float& o0, float& o1) {
    u64 z  = pack2(x0, x1);
    u64 ax = z & 0x7FFFFFFF7FFFFFFFull;
    u64 y  = mul2(ax, bcast2(-2.0f));                      // -2|x|
    // exp(y), Cephes, packed
    u64 t  = ffma2(y, bcast2(1.44269504088896341f), bcast2(12582912.0f));
    u64 n2 = add2(t, bcast2(-12582912.0f));
    u64 r  = ffma2(n2, bcast2(-0.693359375f), y);
    r = ffma2(n2, bcast2(2.12194440e-4f), r);
    u64 p = ffma2(bcast2(1.9875691500e-4f), r, bcast2(1.3981999507e-3f));
    p = ffma2(p, r, bcast2(8.3334519073e-3f));
    p = ffma2(p, r, bcast2(4.1665795894e-2f));
    p = ffma2(p, r, bcast2(1.6666665459e-1f));
    p = ffma2(p, r, bcast2(5.0000001201e-1f));
    u64 rr = mul2(r, r);
    u64 er = add2(ffma2(rr, p, r), bcast2(1.0f));
    float nlo, nhi; unpack2(n2, nlo, nhi);
    float sl = __int_as_float(((int)nlo + 127) << 23);
    float sh = __int_as_float(((int)nhi + 127) << 23);
    u64 e = mul2(er, pack2(sl, sh));
    // (1-e) / (1+e) with packed Newton reciprocal
    u64 num = add2(bcast2(1.0f), e ^ 0x8000000080000000ull);
    u64 den = add2(bcast2(1.0f), e);
    float dlo, dhi; unpack2(den, dlo, dhi);
    u64 rc = pack2(__int_as_float(0x7EF311C3 - __float_as_int(dlo)),
                   __int_as_float(0x7EF311C3 - __float_as_int(dhi)));
    u64 nd = den ^ 0x8000000080000000ull;
    rc = mul2(rc, ffma2(nd, rc, bcast2(2.0f)));
    rc = mul2(rc, ffma2(nd, rc, bcast2(2.0f)));
    rc = ffma2(ffma2(nd, rc, bcast2(1.0f)), rc, rc);
    u64 q = mul2(num, rc);
    float qlo, qhi; unpack2(q, qlo, qhi);
    if (fabsf(x0) > 9.0f) qlo = 1.0f;
    if (fabsf(x1) > 9.0f) qhi = 1.0f;
    o0 = copysignf(qlo, x0);
    o1 = copysignf(qhi, x1);
}

// ---------------- XLA ErfInv32 ----------------------------------------------
__device__ __forceinline__ float jax_erfinv(float x) {
    float w = -log1pf(-__fmul_rn(x, x));
    float p;
    if (w < 5.0f) {
        w = __fadd_rn(w, -2.5f);
        p = 2.81022636e-08f;
        p = fmaf(p, w, 3.43273939e-07f);
        p = fmaf(p, w, -3.5233877e-06f);
        p = fmaf(p, w, -4.39150654e-06f);
        p = fmaf(p, w, 0.00021858087f);
        p = fmaf(p, w, -0.00125372503f);
        p = fmaf(p, w, -0.00417768164f);
        p = fmaf(p, w, 0.246640727f);
        p = fmaf(p, w, 1.50140941f);
    } else {
        w = __fadd_rn(sqrtf(w), -3.0f);
        p = -0.000200214257f;
        p = fmaf(p, w, 0.000100950558f);
        p = fmaf(p, w, 0.00134934322f);
        p = fmaf(p, w, -0.00367342844f);
        p = fmaf(p, w, 0.00573950773f);
        p = fmaf(p, w, -0.0076224613f);
        p = fmaf(p, w, 0.00943887047f);
        p = fmaf(p, w, 1.00167406f);
        p = fmaf(p, w, 2.83297682f);
    }
    return __fmul_rn(p, x);
}

__device__ __forceinline__ float bits_to_unit(unsigned bits) {
    return __fadd_rn(__uint_as_float((bits >> 9) | 0x3f800000u), -1.0f);
}

__device__ __forceinline__ float bits_to_normal(unsigned bits) {
    const float lo = __uint_as_float(0xbf7fffffu);
    float f = bits_to_unit(bits);
    float u = __fadd_rn(__fmul_rn(f, 2.0f), lo);
    u = fmaxf(u, lo);
    return __fmul_rn(__uint_as_float(0x3fb504f3u), jax_erfinv(u));
}

// ---------------- device scratch --------------------------------------------
__device__ float4   g_state[NROWS * 12];
__device__ unsigned g_keysA[NROWS], g_keysB[NROWS];
__device__ unsigned g_valsA[NROWS], g_valsB[NROWS];
__device__ unsigned g_hist[NROWS];      // 256 digits x 256 blocks
__device__ unsigned g_rowsum[256];
__device__ unsigned g_rowoff[256];

struct StepKeys { unsigned k[NSTEP][4][2]; };

// ---------------- fused MH chain kernel -------------------------------------
#define SMEM_FLOATS (DFEAT*HID + HID + HID + ROWS_PB*DFEAT + ROWS_PB*DFEAT)
#define SMEM_BYTES  (SMEM_FLOATS * 4)

__device__ __forceinline__ void eval_rows(const float* __restrict__ buf,
                                          const float* __restrict__ sW,
                                          const float* __restrict__ sb,
                                          const float* __restrict__ sw2,
                                          int r0, int lane, float la[4]) {
    u64 acc[4][4];
#pragma unroll
    for (int r = 0; r < 4; r++)
#pragma unroll
        for (int j = 0; j < 4; j++) acc[r][j] = 0ull;

#pragma unroll 4
    for (int k = 0; k < DFEAT; k += 4) {
#pragma unroll
        for (int kk = 0; kk < 4; kk++) {
            ulonglong2 w0 = *(const ulonglong2*)&sW[(k + kk) * HID + lane * 4];
            ulonglong2 w1 = *(const ulonglong2*)&sW[(k + kk) * HID + 128 + lane * 4];
#pragma unroll
            for (int r = 0; r < 4; r++) {
                float fk = buf[(r0 + r) * DFEAT + k + kk];
                u64 f2 = pack2(fk, fk);
                acc[r][0] = ffma2(f2, w0.x, acc[r][0]);
                acc[r][1] = ffma2(f2, w0.y, acc[r][1]);
                acc[r][2] = ffma2(f2, w1.x, acc[r][2]);
                acc[r][3] = ffma2(f2, w1.y, acc[r][3]);
            }
        }
    }
    float4 b0 = *(const float4*)&sb[lane * 4];
    float4 b1 = *(const float4*)&sb[128 + lane * 4];
    float4 v0 = *(const float4*)&sw2[lane * 4];
    float4 v1 = *(const float4*)&sw2[128 + lane * 4];
#pragma unroll
    for (int r = 0; r < 4; r++) {
        float a0, a1, a2, a3, a4, a5, a6, a7;
        unpack2(acc[r][0], a0, a1);
        unpack2(acc[r][1], a2, a3);
        unpack2(acc[r][2], a4, a5);
        unpack2(acc[r][3], a6, a7);
        // bias add kept scalar (same ops/order as before)
        float t0, t1, t2, t3, t4, t5, t6, t7;
        tanh2(a0 + b0.x, a1 + b0.y, t0, t1);
        tanh2(a2 + b0.z, a3 + b0.w, t2, t3);
        tanh2(a4 + b1.x, a5 + b1.y, t4, t5);
        tanh2(a6 + b1.z, a7 + b1.w, t6, t7);
        // dot kept scalar in the original order (bit-identical la)
        float s = t0 * v0.x;
        s = fmaf(t1, v0.y, s);
        s = fmaf(t2, v0.z, s);
        s = fmaf(t3, v0.w, s);
        s = fmaf(t4, v1.x, s);
        s = fmaf(t5, v1.y, s);
        s = fmaf(t6, v1.z, s);
        s = fmaf(t7, v1.w, s);
#pragma unroll
        for (int off = 16; off; off >>= 1)
            s += __shfl_xor_sync(0xffffffffu, s, off);
        la[r] = s;
    }
}

__global__ void __launch_bounds__(256, 2)
chain_kernel(const float* __restrict__ x,
             const float* __restrict__ W1, const float* __restrict__ b1,
             const float* __restrict__ w2, const float* __restrict__ Wh,
             const float* __restrict__ bh, const float* __restrict__ wh2,
             StepKeys sk) {
    extern __shared__ float smem[];
    float* sW  = smem;
    float* sb  = sW + DFEAT * HID;
    float* sw2 = sb + HID;
    float* sS  = sw2 + HID;
    float* sP  = sS + ROWS_PB * DFEAT;

    int tid = threadIdx.x;
    int half = (int)(blockIdx.x >> 10);
    int localBase = (int)(blockIdx.x & 1023) * ROWS_PB;
    int rowBase = half * HALFN + localBase;

    const float* W  = half ? Wh  : W1;
    const float* bb = half ? bh  : b1;
    const float* vv = half ? wh2 : w2;

    for (int i = tid; i < DFEAT * HID; i += 256) sW[i] = W[i];
    sb[tid]  = bb[tid];
    sw2[tid] = vv[tid];
    {
        const float4* xin = (const float4*)x;
        float4* s4 = (float4*)sS;
        for (int e = tid; e < ROWS_PB * 12; e += 256)
            s4[e] = xin[rowBase * 12 + e];
    }
    __syncthreads();

    int warp = tid >> 5, lane = tid & 31;
    int r0 = warp * 4;

    float la[4], pcur[4];
    eval_rows(sS, sW, sb, sw2, r0, lane, la);
#pragma unroll
    for (int r = 0; r < 4; r++) pcur[r] = my_expf(__fmul_rn(2.0f, la[r]));

    for (int t = 0; t < NSTEP; t++) {
        __syncthreads();
        unsigned n0 = sk.k[t][half ? 1 : 0][0], n1 = sk.k[t][half ? 1 : 0][1];
        unsigned u0 = sk.k[t][half ? 3 : 2][0], u1 = sk.k[t][half ? 3 : 2][1];

        for (int e = tid; e < ROWS_PB * DFEAT; e += 256) {
            unsigned flat = (unsigned)(localBase * DFEAT + e);
            float nrm = bits_to_normal(rbits(n0, n1, flat));
            sP[e] = __fadd_rn(sS[e], __fmul_rn(0.02f, nrm));
        }
        __syncthreads();

        eval_rows(sP, sW, sb, sw2, r0, lane, la);
#pragma unroll
        for (int r = 0; r < 4; r++) {
            float pnew = my_expf(__fmul_rn(2.0f, la[r]));
            float uu = bits_to_unit(rbits(u0, u1, (unsigned)(localBase + r0 + r)));
            if (pnew / pcur[r] > uu) {          // warp-uniform branch
                pcur[r] = pnew;
                int base = (r0 + r) * DFEAT;
                sS[base + lane] = sP[base + lane];
                if (lane < 16) sS[base + 32 + lane] = sP[base + 32 + lane];
            }
        }
    }
    __syncthreads();
    {
        float4* s4 = (float4*)sS;
        for (int e = tid; e < ROWS_PB * 12; e += 256)
            g_state[rowBase * 12 + e] = s4[e];
    }
}

// ---------------- permutation: 2 rounds of stable LSD radix sort ------------
__global__ void genkeys_kernel(unsigned k0, unsigned k1, int initVals) {
    int i = blockIdx.x * blockDim.x + threadIdx.x;
    g_keysA[i] = rbits(k0, k1, (unsigned)i);
    if (initVals) g_valsA[i] = (unsigned)i;
}

__global__ void radix_count(int srcB, int shift) {
    __shared__ unsigned h[256];
    const unsigned* keys = srcB ? g_keysB : g_keysA;
    h[threadIdx.x] = 0;
    __syncthreads();
    unsigned d = (keys[blockIdx.x * 256 + threadIdx.x] >> shift) & 255u;
    atomicAdd(&h[d], 1u);
    __syncthreads();
    g_hist[threadIdx.x * 256 + blockIdx.x] = h[threadIdx.x];
}

// per-digit-row exclusive scan: 256 blocks x 256 threads
__global__ void radix_scan_rows() {
    __shared__ unsigned wsum[8];
    int d = blockIdx.x, t = threadIdx.x, lane = t & 31, w = t >> 5;
    unsigned v = g_hist[d * 256 + t];
    unsigned inc = v;
#pragma unroll
    for (int off = 1; off < 32; off <<= 1) {
        unsigned tmp = __shfl_up_sync(0xffffffffu, inc, off);
        if (lane >= off) inc += tmp;
    }
    if (lane == 31) wsum[w] = inc;
    __syncthreads();
    unsigned woff = 0;
#pragma unroll
    for (int i = 0; i < 8; i++) woff += (i < w) ? wsum[i] : 0u;
    unsigned exc = inc - v + woff;
    g_hist[d * 256 + t] = exc;
    if (t == 255) g_rowsum[d] = exc + v;
}

// scan of the 256 row totals: 1 block x 256 threads
__global__ void radix_scan_tot() {
    __shared__ unsigned wsum[8];
    int t = threadIdx.x, lane = t & 31, w = t >> 5;
    unsigned v = g_rowsum[t];
    unsigned inc = v;
#pragma unroll
    for (int off = 1; off < 32; off <<= 1) {
        unsigned tmp = __shfl_up_sync(0xffffffffu, inc, off);
        if (lane >= off) inc += tmp;
    }
    if (lane == 31) wsum[w] = inc;
    __syncthreads();
    unsigned woff = 0;
#pragma unroll
    for (int i = 0; i < 8; i++) woff += (i < w) ? wsum[i] : 0u;
    g_rowoff[t] = inc - v + woff;
}

// stable scatter with warp-ballot ranking
__global__ void radix_scatter(int srcB, int shift) {
    __shared__ unsigned wh[8][256];     // per-warp per-digit counts
    const unsigned* kin = srcB ? g_keysB : g_keysA;
    const unsigned* vin = srcB ? g_valsB : g_valsA;
    unsigned* kout = srcB ? g_keysA : g_keysB;
    unsigned* vout = srcB ? g_valsA : g_valsB;
    int t = threadIdx.x, w = t >> 5, lane = t & 31;
#pragma unroll
    for (int i = 0; i < 8; i++) wh[i][t] = 0;
    __syncthreads();

    int i = blockIdx.x * 256 + t;
    unsigned k = kin[i];
    unsigned v = vin[i];
    unsigned d = (k >> shift) & 255u;
    unsigned mask = __match_any_sync(0xffffffffu, d);
    unsigned rankw = __popc(mask & ((1u << lane) - 1u));
    if (rankw == 0) wh[w][d] = __popc(mask);   // leader publishes warp count
    __syncthreads();
    unsigned prev = 0;
#pragma unroll
    for (int j = 0; j < 8; j++) prev += (j < w) ? wh[j][d] : 0u;
    unsigned pos = g_hist[d * 256 + blockIdx.x] + g_rowoff[d] + prev + rankw;
    kout[pos] = k;
    vout[pos] = v;
}

__global__ void gather_kernel(float4* __restrict__ out) {
    int idx = blockIdx.x * blockDim.x + threadIdx.x;
    int row = idx / 12, q = idx - row * 12;
    out[idx] = g_state[g_valsA[row] * 12 + q];
}

// ---------------- host ------------------------------------------------------
extern "C" void kernel_launch(void* const* d_in, const int* in_sizes, int n_in,
                              void* d_out, int out_size) {
    (void)in_sizes; (void)n_in; (void)out_size;
    const float* x   = (const float*)d_in[0];
    const float* W1  = (const float*)d_in[1];
    const float* b1  = (const float*)d_in[2];
    const float* w2  = (const float*)d_in[3];
    const float* Wh  = (const float*)d_in[4];
    const float* bh  = (const float*)d_in[5];
    const float* wh2 = (const float*)d_in[6];

    StepKeys sk;
    for (int t = 0; t < NSTEP; t++) {
        unsigned s0, s1;
        tf2x32(0u, 42u, 0u, (unsigned)t, s0, s1);
        for (int j = 0; j < 4; j++)
            tf2x32(s0, s1, 0u, (unsigned)j, sk.k[t][j][0], sk.k[t][j][1]);
    }
    unsigned nk0, nk1, s1a, s1b, s2a, s2b;
    tf2x32(0u, 7u, 0u, 0u, nk0, nk1);
    tf2x32(0u, 7u, 0u, 1u, s1a, s1b);
    tf2x32(nk0, nk1, 0u, 1u, s2a, s2b);

    cudaFuncSetAttribute(chain_kernel,
                         cudaFuncAttributeMaxDynamicSharedMemorySize, SMEM_BYTES);
    chain_kernel<<<NBLOCKS, 256, SMEM_BYTES>>>(x, W1, b1, w2, Wh, bh, wh2, sk);

    for (int round = 0; round < 2; round++) {
        if (round == 0) genkeys_kernel<<<NROWS / 256, 256>>>(s1a, s1b, 1);
        else            genkeys_kernel<<<NROWS / 256, 256>>>(s2a, s2b, 0);
        for (int pass = 0; pass < 4; pass++) {
            radix_count<<<256, 256>>>(pass & 1, pass * 8);
            radix_scan_rows<<<256, 256>>>();
            radix_scan_tot<<<1, 256>>>();
            radix_scatter<<<256, 256>>>(pass & 1, pass * 8);
        }
    }
    gather_kernel<<<NROWS * 12 / 256, 256>>>((float4*)d_out);
}